// round 14
// baseline (speedup 1.0000x reference)
#include <cuda_runtime.h>
#include <cstdint>
#include <math.h>

// ---------------------------------------------------------------------------
// Problem constants
// ---------------------------------------------------------------------------
static constexpr int Bn = 32;
static constexpr int Sn = 1024;
static constexpr int En = 512;
static constexpr int Hn = 8;
static constexpr int Dn = 64;       // E / H
static constexpr int Ln = 2;
static constexpr int Mn = Bn * Sn;  // 32768 rows
static constexpr size_t ME = (size_t)Mn * En;  // 16,777,216 elements

// Scratch arena: X, Q, K, V, Attn (5 * 64MB) + PE table (2MB)
__device__ float g_buf[5 * ME + (size_t)Sn * En];

// ---------------------------------------------------------------------------
// Helpers
// ---------------------------------------------------------------------------
__device__ __forceinline__ uint64_t pack2(float lo, float hi) {
    uint64_t r;
    asm("mov.b64 %0, {%1, %2};" : "=l"(r) : "f"(lo), "f"(hi));
    return r;
}
__device__ __forceinline__ void fma2(uint64_t& d, uint64_t a, uint64_t b) {
    asm("fma.rn.f32x2 %0, %1, %2, %0;" : "+l"(d) : "l"(a), "l"(b));
}
__device__ __forceinline__ void mul2(uint64_t& d, uint64_t a, uint64_t b) {
    asm("mul.rn.f32x2 %0, %1, %2;" : "=l"(d) : "l"(a), "l"(b));
}
__device__ __forceinline__ float2 unpack2(uint64_t v) {
    float2 f;
    asm("mov.b64 {%0, %1}, %2;" : "=f"(f.x), "=f"(f.y) : "l"(v));
    return f;
}
__device__ __forceinline__ float ex2(float x) {
    float r;
    asm("ex2.approx.ftz.f32 %0, %1;" : "=f"(r) : "f"(x));
    return r;
}
__device__ __forceinline__ uint32_t smem_u32(const void* p) {
    uint32_t a;
    asm("{ .reg .u64 t; cvta.to.shared.u64 t, %1; cvt.u32.u64 %0, t; }" : "=r"(a) : "l"(p));
    return a;
}
__device__ __forceinline__ void cp16(uint32_t s, const void* g) {
    asm volatile("cp.async.cg.shared.global [%0], [%1], 16;" :: "r"(s), "l"(g));
}
__device__ __forceinline__ void cp_commit() {
    asm volatile("cp.async.commit_group;");
}
__device__ __forceinline__ void cp_wait_all() {
    asm volatile("cp.async.wait_group 0;");
}

// ---------------------------------------------------------------------------
// Positional encoding table
// ---------------------------------------------------------------------------
__global__ void pe_kernel(float* __restrict__ pe) {
    int idx = blockIdx.x * blockDim.x + threadIdx.x;
    if (idx >= Sn * En) return;
    int s = idx >> 9;
    int e = idx & 511;
    float i2 = (float)(e & ~1);
    float div = __expf(i2 * (-9.210340371976184f / (float)En));
    float a = (float)s * div;
    pe[idx] = (e & 1) ? cosf(a) : sinf(a);
}

// ---------------------------------------------------------------------------
// Embedding gather + PE add
// ---------------------------------------------------------------------------
__global__ void embed_kernel(const int* __restrict__ tok,
                             const float* __restrict__ table,
                             const float* __restrict__ pe,
                             float* __restrict__ x) {
    int idx4 = blockIdx.x * blockDim.x + threadIdx.x;
    if (idx4 >= Mn * (En / 4)) return;
    int row = idx4 >> 7;
    int d4  = idx4 & 127;
    int s   = row & (Sn - 1);
    int t   = tok[row];
    float4 tv = ((const float4*)table)[(size_t)t * 128 + d4];
    float4 pv = ((const float4*)pe)[(size_t)s * 128 + d4];
    float4 o;
    o.x = tv.x + pv.x; o.y = tv.y + pv.y; o.z = tv.z + pv.z; o.w = tv.w + pv.w;
    ((float4*)x)[idx4] = o;
}

// ---------------------------------------------------------------------------
// SGEMM (R5 proven): cp.async double-buffered, FFMA2 inner, 128x128x16.
// ---------------------------------------------------------------------------
template <bool RELU_RES>
__global__ __launch_bounds__(256, 2)
void gemm512(const float* __restrict__ A, const float* __restrict__ W,
             const float* __restrict__ bias, const float* __restrict__ res,
             float* __restrict__ C) {
    __shared__ float As[2][128 * 16];
    __shared__ float Bs[2][16 * 128];
    const int tid = threadIdx.x;
    const int tx = tid & 15;
    const int ty = tid >> 4;
    const int row0 = blockIdx.y * 128;
    const int col0 = blockIdx.x * 128;
    const uint32_t aS = smem_u32(As[0]);
    const uint32_t bS = smem_u32(Bs[0]);

    uint64_t acc2[8][4];
#pragma unroll
    for (int i = 0; i < 8; ++i)
#pragma unroll
        for (int j = 0; j < 4; ++j) acc2[i][j] = 0ull;

    auto issue = [&](int c) {
        const int buf = c & 1;
        const uint32_t ab = aS + buf * (128 * 16 * 4);
        const uint32_t bb = bS + buf * (16 * 128 * 4);
        const float* Ag = A + (size_t)row0 * En + c * 16;
        const float* Wg = W + (size_t)(c * 16) * En + col0;
#pragma unroll
        for (int i = 0; i < 2; ++i) {
            int idx = tid + i * 256;
            int m = idx >> 2, k4 = idx & 3;
            cp16(ab + (m * 16 + k4 * 4) * 4, Ag + (size_t)m * En + k4 * 4);
        }
#pragma unroll
        for (int i = 0; i < 2; ++i) {
            int idx = tid + i * 256;
            int kk = idx >> 5, n4 = idx & 31;
            cp16(bb + (kk * 128 + n4 * 4) * 4, Wg + (size_t)kk * En + n4 * 4);
        }
        cp_commit();
    };

    issue(0);
    for (int c = 0; c < 32; ++c) {
        cp_wait_all();
        __syncthreads();
        if (c < 31) issue(c + 1);
        const float* as_ = As[c & 1];
        const float* bs_ = Bs[c & 1];
#pragma unroll
        for (int kk = 0; kk < 16; ++kk) {
            ulonglong2 b01 = *(const ulonglong2*)&bs_[kk * 128 + tx * 4];
            ulonglong2 b23 = *(const ulonglong2*)&bs_[kk * 128 + 64 + tx * 4];
#pragma unroll
            for (int i = 0; i < 8; ++i) {
                float a = as_[(ty * 8 + i) * 16 + kk];
                uint64_t av = pack2(a, a);
                fma2(acc2[i][0], av, b01.x);
                fma2(acc2[i][1], av, b01.y);
                fma2(acc2[i][2], av, b23.x);
                fma2(acc2[i][3], av, b23.y);
            }
        }
    }

    float4 bi0 = *(const float4*)&bias[col0 + tx * 4];
    float4 bi1 = *(const float4*)&bias[col0 + 64 + tx * 4];
#pragma unroll
    for (int i = 0; i < 8; ++i) {
        int m = row0 + ty * 8 + i;
        size_t off0 = (size_t)m * En + col0 + tx * 4;
        size_t off1 = off0 + 64;
        float2 p0 = unpack2(acc2[i][0]);
        float2 p1 = unpack2(acc2[i][1]);
        float2 p2 = unpack2(acc2[i][2]);
        float2 p3 = unpack2(acc2[i][3]);
        float4 v0, v1;
        v0.x = p0.x + bi0.x; v0.y = p0.y + bi0.y;
        v0.z = p1.x + bi0.z; v0.w = p1.y + bi0.w;
        v1.x = p2.x + bi1.x; v1.y = p2.y + bi1.y;
        v1.z = p3.x + bi1.z; v1.w = p3.y + bi1.w;
        if (RELU_RES) {
            float4 r0 = *(const float4*)&res[off0];
            float4 r1 = *(const float4*)&res[off1];
            v0.x = r0.x + fmaxf(v0.x, 0.f); v0.y = r0.y + fmaxf(v0.y, 0.f);
            v0.z = r0.z + fmaxf(v0.z, 0.f); v0.w = r0.w + fmaxf(v0.w, 0.f);
            v1.x = r1.x + fmaxf(v1.x, 0.f); v1.y = r1.y + fmaxf(v1.y, 0.f);
            v1.z = r1.z + fmaxf(v1.z, 0.f); v1.w = r1.w + fmaxf(v1.w, 0.f);
        }
        *(float4*)&C[off0] = v0;
        *(float4*)&C[off1] = v1;
    }
}

// ---------------------------------------------------------------------------
// Causal flash attention: KT=64 double-buffered, one sync per tile,
// 4-chain depth-8 score dot, MUFU ex2 softmax.
// __launch_bounds__(128, 3): cap regs at 170 -> 3 blocks/SM (12 warps),
// fixing the regs=182 / occ=12% collapse measured in R13.
// ---------------------------------------------------------------------------
static constexpr int KT = 64;
static constexpr int ATT_SMEM = 2 * 2 * KT * Dn * (int)sizeof(float);  // 65536
static constexpr float SC2 = 0.18033688011112042f;  // (1/8) * log2(e)

__global__ __launch_bounds__(128, 3)
void attn_kernel(const float* __restrict__ Q, const float* __restrict__ Kg,
                 const float* __restrict__ Vg, float* __restrict__ Og) {
    extern __shared__ float smA[];   // [buf][K(4096) | V(4096)]
    const uint32_t sS = smem_u32(smA);
    const int b = blockIdx.z, h = blockIdx.y, qt = blockIdx.x;
    const int r = threadIdx.x;
    const int qg = qt * 128 + r;

    const ulonglong2* qp = (const ulonglong2*)(Q + ((size_t)(b * Sn + qg)) * En + h * Dn);
    uint64_t q2[32];
#pragma unroll
    for (int i = 0; i < 16; ++i) {
        ulonglong2 t = qp[i];
        q2[2 * i] = t.x; q2[2 * i + 1] = t.y;
    }
    uint64_t o2[32];
#pragma unroll
    for (int i = 0; i < 32; ++i) o2[i] = 0ull;

    float mi = -1e30f, l = 0.f;
    const int nkt = qt * 2 + 2;      // 64-key tiles up to & incl. diagonal

    auto issue_tile = [&](int kt) {
        size_t base = ((size_t)(b * Sn + kt * KT)) * En + h * Dn;
        uint32_t kd = sS + (kt & 1) * 32768;
        uint32_t vd = kd + 16384;
#pragma unroll
        for (int i = 0; i < 8; ++i) {           // 1024 cp16 each for K and V
            int idx = r + i * 128;
            int row = idx >> 4, d4 = idx & 15;
            const float* src = Kg + base + (size_t)row * En + d4 * 4;
            const float* srv = Vg + base + (size_t)row * En + d4 * 4;
            uint32_t off = (row * 64 + d4 * 4) * 4;
            cp16(kd + off, src);
            cp16(vd + off, srv);
        }
        cp_commit();
    };

    issue_tile(0);
    for (int kt = 0; kt < nkt; ++kt) {
        cp_wait_all();
        __syncthreads();
        if (kt + 1 < nkt) issue_tile(kt + 1);   // overlaps compute below

        const float* Ks = smA + (kt & 1) * 8192;
        const float* Vs = Ks + 4096;
        const bool masked = (kt >= qt * 2);     // only diagonal-straddling tiles
        const int kbase = kt * KT;

        float s[KT];
        float tmax = -1e30f;
#pragma unroll 4
        for (int j = 0; j < KT; ++j) {
            const ulonglong2* kr = (const ulonglong2*)(Ks + j * 64);
            uint64_t c0 = 0ull, c1 = 0ull, c2c = 0ull, c3 = 0ull;  // 4 chains, depth 8
#pragma unroll
            for (int d = 0; d < 8; ++d) {       // kr[0..15]: all 64 dims
                ulonglong2 kva = kr[2 * d];
                ulonglong2 kvb = kr[2 * d + 1];
                fma2(c0,  q2[4 * d],     kva.x);
                fma2(c1,  q2[4 * d + 1], kva.y);
                fma2(c2c, q2[4 * d + 2], kvb.x);
                fma2(c3,  q2[4 * d + 3], kvb.y);
            }
            float2 f0 = unpack2(c0), f1 = unpack2(c1);
            float2 f2 = unpack2(c2c), f3 = unpack2(c3);
            float sj = ((f0.x + f0.y) + (f1.x + f1.y))
                     + ((f2.x + f2.y) + (f3.x + f3.y));
            sj *= SC2;                                  // exp2 domain
            if (masked && (kbase + j > qg)) sj = -1e30f;
            s[j] = sj;
            tmax = fmaxf(tmax, sj);
        }

        float mnew = fmaxf(mi, tmax);
        float corr = ex2(mi - mnew);
        l *= corr;
        uint64_t cc = pack2(corr, corr);
#pragma unroll
        for (int d = 0; d < 32; ++d) mul2(o2[d], o2[d], cc);
#pragma unroll 4
        for (int j = 0; j < KT; ++j) {
            float p = ex2(s[j] - mnew);
            l += p;
            uint64_t p2 = pack2(p, p);
            const ulonglong2* vr = (const ulonglong2*)(Vs + j * 64);
#pragma unroll
            for (int d = 0; d < 16; ++d) {
                ulonglong2 vv = vr[d];
                fma2(o2[2 * d],     p2, vv.x);
                fma2(o2[2 * d + 1], p2, vv.y);
            }
        }
        mi = mnew;
    }

    float inv = 1.f / l;
    float4* op = (float4*)(Og + ((size_t)(b * Sn + qg)) * En + h * Dn);
#pragma unroll
    for (int i = 0; i < 16; ++i) {
        float2 lo = unpack2(o2[2 * i]);
        float2 hi = unpack2(o2[2 * i + 1]);
        float4 v;
        v.x = lo.x * inv; v.y = lo.y * inv;
        v.z = hi.x * inv; v.w = hi.y * inv;
        op[i] = v;
    }
}

// ---------------------------------------------------------------------------
// Final head: out[m] = X[m,:] . W_out[:,0] + b_out   (warp per row)
// ---------------------------------------------------------------------------
__global__ void head_kernel(const float* __restrict__ X,
                            const float* __restrict__ Wout,
                            const float* __restrict__ bout,
                            float* __restrict__ out) {
    int gw = (blockIdx.x * blockDim.x + threadIdx.x) >> 5;
    int lane = threadIdx.x & 31;
    if (gw >= Mn) return;
    const float4* xr = (const float4*)(X + (size_t)gw * En);
    const float4* w4 = (const float4*)Wout;
    float acc = 0.f;
#pragma unroll
    for (int i = 0; i < 4; ++i) {
        float4 xv = xr[lane + i * 32];
        float4 wv = w4[lane + i * 32];
        acc += xv.x * wv.x + xv.y * wv.y + xv.z * wv.z + xv.w * wv.w;
    }
#pragma unroll
    for (int o = 16; o > 0; o >>= 1)
        acc += __shfl_xor_sync(0xffffffffu, acc, o);
    if (lane == 0) out[gw] = acc + bout[0];
}

// ---------------------------------------------------------------------------
// Launch
// ---------------------------------------------------------------------------
extern "C" void kernel_launch(void* const* d_in, const int* in_sizes, int n_in,
                              void* d_out, int out_size) {
    const int*   tok   = (const int*)d_in[0];
    const float* table = (const float*)d_in[1];
    const float* Wq    = (const float*)d_in[2];
    const float* bq    = (const float*)d_in[3];
    const float* Wk    = (const float*)d_in[4];
    const float* bk    = (const float*)d_in[5];
    const float* Wv    = (const float*)d_in[6];
    const float* bv    = (const float*)d_in[7];
    const float* Wo    = (const float*)d_in[8];
    const float* bo    = (const float*)d_in[9];
    const float* Wout  = (const float*)d_in[10];
    const float* bout  = (const float*)d_in[11];
    float* out = (float*)d_out;

    void* base = nullptr;
    cudaGetSymbolAddress(&base, g_buf);   // not a stream op: capture-safe
    float* X  = (float*)base;
    float* Qb = X + ME;
    float* Kb = X + 2 * ME;
    float* Vb = X + 3 * ME;
    float* Ab = X + 4 * ME;
    float* PE = X + 5 * ME;

    static bool attr_done = false;
    if (!attr_done) {
        cudaFuncSetAttribute(attn_kernel, cudaFuncAttributeMaxDynamicSharedMemorySize, ATT_SMEM);
        attr_done = true;
    }

    pe_kernel<<<(Sn * En + 255) / 256, 256>>>(PE);
    embed_kernel<<<(Mn * (En / 4) + 255) / 256, 256>>>(tok, table, PE, X);

    dim3 gg(En / 128, Mn / 128);   // (4, 256)
    dim3 ag(Sn / 128, Hn, Bn);     // (8, 8, 32)
    for (int l = 0; l < Ln; ++l) {
        const float* wq = Wq + (size_t)l * En * En; const float* bql = bq + l * En;
        const float* wk = Wk + (size_t)l * En * En; const float* bkl = bk + l * En;
        const float* wv = Wv + (size_t)l * En * En; const float* bvl = bv + l * En;
        const float* wo = Wo + (size_t)l * En * En; const float* bol = bo + l * En;
        gemm512<false><<<gg, 256>>>(X,  wq, bql, nullptr, Qb);
        gemm512<false><<<gg, 256>>>(X,  wk, bkl, nullptr, Kb);
        gemm512<false><<<gg, 256>>>(X,  wv, bvl, nullptr, Vb);
        attn_kernel<<<ag, 128, ATT_SMEM>>>(Qb, Kb, Vb, Ab);
        gemm512<true><<<gg, 256>>>(Ab, wo, bol, X, X);   // X = X + relu(attn@Wo+bo)
    }
    head_kernel<<<(Mn * 32 + 255) / 256, 256>>>(X, Wout, bout, out);
}

// round 16
// speedup vs baseline: 1.0364x; 1.0364x over previous
#include <cuda_runtime.h>
#include <cstdint>
#include <math.h>

// ---------------------------------------------------------------------------
// Problem constants
// ---------------------------------------------------------------------------
static constexpr int Bn = 32;
static constexpr int Sn = 1024;
static constexpr int En = 512;
static constexpr int Hn = 8;
static constexpr int Dn = 64;       // E / H
static constexpr int Ln = 2;
static constexpr int Mn = Bn * Sn;  // 32768 rows
static constexpr size_t ME = (size_t)Mn * En;  // 16,777,216 elements

// Scratch arena: X, Q, K, V, Attn (5 * 64MB) + PE table (2MB)
__device__ float g_buf[5 * ME + (size_t)Sn * En];

// ---------------------------------------------------------------------------
// Helpers
// ---------------------------------------------------------------------------
__device__ __forceinline__ uint64_t pack2(float lo, float hi) {
    uint64_t r;
    asm("mov.b64 %0, {%1, %2};" : "=l"(r) : "f"(lo), "f"(hi));
    return r;
}
__device__ __forceinline__ void fma2(uint64_t& d, uint64_t a, uint64_t b) {
    asm("fma.rn.f32x2 %0, %1, %2, %0;" : "+l"(d) : "l"(a), "l"(b));
}
__device__ __forceinline__ void mul2(uint64_t& d, uint64_t a, uint64_t b) {
    asm("mul.rn.f32x2 %0, %1, %2;" : "=l"(d) : "l"(a), "l"(b));
}
__device__ __forceinline__ float2 unpack2(uint64_t v) {
    float2 f;
    asm("mov.b64 {%0, %1}, %2;" : "=f"(f.x), "=f"(f.y) : "l"(v));
    return f;
}
__device__ __forceinline__ float ex2(float x) {
    float r;
    asm("ex2.approx.ftz.f32 %0, %1;" : "=f"(r) : "f"(x));
    return r;
}
__device__ __forceinline__ uint32_t smem_u32(const void* p) {
    uint32_t a;
    asm("{ .reg .u64 t; cvta.to.shared.u64 t, %1; cvt.u32.u64 %0, t; }" : "=r"(a) : "l"(p));
    return a;
}
__device__ __forceinline__ void cp16(uint32_t s, const void* g) {
    asm volatile("cp.async.cg.shared.global [%0], [%1], 16;" :: "r"(s), "l"(g));
}
__device__ __forceinline__ void cp_commit() {
    asm volatile("cp.async.commit_group;");
}
__device__ __forceinline__ void cp_wait_all() {
    asm volatile("cp.async.wait_group 0;");
}

// ---------------------------------------------------------------------------
// Positional encoding table
// ---------------------------------------------------------------------------
__global__ void pe_kernel(float* __restrict__ pe) {
    int idx = blockIdx.x * blockDim.x + threadIdx.x;
    if (idx >= Sn * En) return;
    int s = idx >> 9;
    int e = idx & 511;
    float i2 = (float)(e & ~1);
    float div = __expf(i2 * (-9.210340371976184f / (float)En));
    float a = (float)s * div;
    pe[idx] = (e & 1) ? cosf(a) : sinf(a);
}

// ---------------------------------------------------------------------------
// Embedding gather + PE add
// ---------------------------------------------------------------------------
__global__ void embed_kernel(const int* __restrict__ tok,
                             const float* __restrict__ table,
                             const float* __restrict__ pe,
                             float* __restrict__ x) {
    int idx4 = blockIdx.x * blockDim.x + threadIdx.x;
    if (idx4 >= Mn * (En / 4)) return;
    int row = idx4 >> 7;
    int d4  = idx4 & 127;
    int s   = row & (Sn - 1);
    int t   = tok[row];
    float4 tv = ((const float4*)table)[(size_t)t * 128 + d4];
    float4 pv = ((const float4*)pe)[(size_t)s * 128 + d4];
    float4 o;
    o.x = tv.x + pv.x; o.y = tv.y + pv.y; o.z = tv.z + pv.z; o.w = tv.w + pv.w;
    ((float4*)x)[idx4] = o;
}

// ---------------------------------------------------------------------------
// SGEMM (R5 proven): cp.async double-buffered, FFMA2 inner, 128x128x16.
// ---------------------------------------------------------------------------
template <bool RELU_RES>
__global__ __launch_bounds__(256, 2)
void gemm512(const float* __restrict__ A, const float* __restrict__ W,
             const float* __restrict__ bias, const float* __restrict__ res,
             float* __restrict__ C) {
    __shared__ float As[2][128 * 16];
    __shared__ float Bs[2][16 * 128];
    const int tid = threadIdx.x;
    const int tx = tid & 15;
    const int ty = tid >> 4;
    const int row0 = blockIdx.y * 128;
    const int col0 = blockIdx.x * 128;
    const uint32_t aS = smem_u32(As[0]);
    const uint32_t bS = smem_u32(Bs[0]);

    uint64_t acc2[8][4];
#pragma unroll
    for (int i = 0; i < 8; ++i)
#pragma unroll
        for (int j = 0; j < 4; ++j) acc2[i][j] = 0ull;

    auto issue = [&](int c) {
        const int buf = c & 1;
        const uint32_t ab = aS + buf * (128 * 16 * 4);
        const uint32_t bb = bS + buf * (16 * 128 * 4);
        const float* Ag = A + (size_t)row0 * En + c * 16;
        const float* Wg = W + (size_t)(c * 16) * En + col0;
#pragma unroll
        for (int i = 0; i < 2; ++i) {
            int idx = tid + i * 256;
            int m = idx >> 2, k4 = idx & 3;
            cp16(ab + (m * 16 + k4 * 4) * 4, Ag + (size_t)m * En + k4 * 4);
        }
#pragma unroll
        for (int i = 0; i < 2; ++i) {
            int idx = tid + i * 256;
            int kk = idx >> 5, n4 = idx & 31;
            cp16(bb + (kk * 128 + n4 * 4) * 4, Wg + (size_t)kk * En + n4 * 4);
        }
        cp_commit();
    };

    issue(0);
    for (int c = 0; c < 32; ++c) {
        cp_wait_all();
        __syncthreads();
        if (c < 31) issue(c + 1);
        const float* as_ = As[c & 1];
        const float* bs_ = Bs[c & 1];
#pragma unroll
        for (int kk = 0; kk < 16; ++kk) {
            ulonglong2 b01 = *(const ulonglong2*)&bs_[kk * 128 + tx * 4];
            ulonglong2 b23 = *(const ulonglong2*)&bs_[kk * 128 + 64 + tx * 4];
#pragma unroll
            for (int i = 0; i < 8; ++i) {
                float a = as_[(ty * 8 + i) * 16 + kk];
                uint64_t av = pack2(a, a);
                fma2(acc2[i][0], av, b01.x);
                fma2(acc2[i][1], av, b01.y);
                fma2(acc2[i][2], av, b23.x);
                fma2(acc2[i][3], av, b23.y);
            }
        }
    }

    float4 bi0 = *(const float4*)&bias[col0 + tx * 4];
    float4 bi1 = *(const float4*)&bias[col0 + 64 + tx * 4];
#pragma unroll
    for (int i = 0; i < 8; ++i) {
        int m = row0 + ty * 8 + i;
        size_t off0 = (size_t)m * En + col0 + tx * 4;
        size_t off1 = off0 + 64;
        float2 p0 = unpack2(acc2[i][0]);
        float2 p1 = unpack2(acc2[i][1]);
        float2 p2 = unpack2(acc2[i][2]);
        float2 p3 = unpack2(acc2[i][3]);
        float4 v0, v1;
        v0.x = p0.x + bi0.x; v0.y = p0.y + bi0.y;
        v0.z = p1.x + bi0.z; v0.w = p1.y + bi0.w;
        v1.x = p2.x + bi1.x; v1.y = p2.y + bi1.y;
        v1.z = p3.x + bi1.z; v1.w = p3.y + bi1.w;
        if (RELU_RES) {
            float4 r0 = *(const float4*)&res[off0];
            float4 r1 = *(const float4*)&res[off1];
            v0.x = r0.x + fmaxf(v0.x, 0.f); v0.y = r0.y + fmaxf(v0.y, 0.f);
            v0.z = r0.z + fmaxf(v0.z, 0.f); v0.w = r0.w + fmaxf(v0.w, 0.f);
            v1.x = r1.x + fmaxf(v1.x, 0.f); v1.y = r1.y + fmaxf(v1.y, 0.f);
            v1.z = r1.z + fmaxf(v1.z, 0.f); v1.w = r1.w + fmaxf(v1.w, 0.f);
        }
        *(float4*)&C[off0] = v0;
        *(float4*)&C[off1] = v1;
    }
}

// ---------------------------------------------------------------------------
// Causal flash attention v6: deferred-rescale online softmax, NO s[] array.
// Per key: score dot (4 chains) -> p = ex2(s - mi) immediately -> l += p,
// o += p*V  (single fused loop). Tile end: one rescale by ex2(mi - mnew).
// Mathematically identical to flash attention; mi starts at 0 (exp2-domain
// scores are O(10), diagonal key guarantees l >= ~1; p <= 2^~12, safe).
// Removes the s[64] local array -> regs ~150, (128,3) fits WITHOUT spills.
// ---------------------------------------------------------------------------
static constexpr int KT = 64;
static constexpr int ATT_SMEM = 2 * 2 * KT * Dn * (int)sizeof(float);  // 65536
static constexpr float SC2 = 0.18033688011112042f;  // (1/8) * log2(e)

__global__ __launch_bounds__(128, 3)
void attn_kernel(const float* __restrict__ Q, const float* __restrict__ Kg,
                 const float* __restrict__ Vg, float* __restrict__ Og) {
    extern __shared__ float smA[];   // [buf][K(4096) | V(4096)]
    const uint32_t sS = smem_u32(smA);
    const int b = blockIdx.z, h = blockIdx.y, qt = blockIdx.x;
    const int r = threadIdx.x;
    const int qg = qt * 128 + r;

    const ulonglong2* qp = (const ulonglong2*)(Q + ((size_t)(b * Sn + qg)) * En + h * Dn);
    uint64_t q2[32];
#pragma unroll
    for (int i = 0; i < 16; ++i) {
        ulonglong2 t = qp[i];
        q2[2 * i] = t.x; q2[2 * i + 1] = t.y;
    }
    uint64_t o2[32];
#pragma unroll
    for (int i = 0; i < 32; ++i) o2[i] = 0ull;

    float mi = 0.f, l = 0.f;         // base 0 is safe in exp2 domain
    const int nkt = qt * 2 + 2;      // 64-key tiles up to & incl. diagonal

    auto issue_tile = [&](int kt) {
        size_t base = ((size_t)(b * Sn + kt * KT)) * En + h * Dn;
        uint32_t kd = sS + (kt & 1) * 32768;
        uint32_t vd = kd + 16384;
#pragma unroll
        for (int i = 0; i < 8; ++i) {           // 1024 cp16 each for K and V
            int idx = r + i * 128;
            int row = idx >> 4, d4 = idx & 15;
            const float* src = Kg + base + (size_t)row * En + d4 * 4;
            const float* srv = Vg + base + (size_t)row * En + d4 * 4;
            uint32_t off = (row * 64 + d4 * 4) * 4;
            cp16(kd + off, src);
            cp16(vd + off, srv);
        }
        cp_commit();
    };

    issue_tile(0);
    for (int kt = 0; kt < nkt; ++kt) {
        cp_wait_all();
        __syncthreads();
        if (kt + 1 < nkt) issue_tile(kt + 1);   // overlaps compute below

        const float* Ks = smA + (kt & 1) * 8192;
        const float* Vs = Ks + 4096;
        const bool masked = (kt >= qt * 2);     // only diagonal-straddling tiles
        const int kbase = kt * KT;

        float tmax = mi;
#pragma unroll 2
        for (int j = 0; j < KT; ++j) {
            // ---- score dot: 4 chains of depth 8 over all 64 dims ----
            const ulonglong2* kr = (const ulonglong2*)(Ks + j * 64);
            uint64_t c0 = 0ull, c1 = 0ull, c2c = 0ull, c3 = 0ull;
#pragma unroll
            for (int d = 0; d < 8; ++d) {
                ulonglong2 kva = kr[2 * d];
                ulonglong2 kvb = kr[2 * d + 1];
                fma2(c0,  q2[4 * d],     kva.x);
                fma2(c1,  q2[4 * d + 1], kva.y);
                fma2(c2c, q2[4 * d + 2], kvb.x);
                fma2(c3,  q2[4 * d + 3], kvb.y);
            }
            float2 f0 = unpack2(c0), f1 = unpack2(c1);
            float2 f2 = unpack2(c2c), f3 = unpack2(c3);
            float sj = (((f0.x + f0.y) + (f1.x + f1.y))
                      + ((f2.x + f2.y) + (f3.x + f3.y))) * SC2;
            if (masked && (kbase + j > qg)) sj = -1e30f;
            tmax = fmaxf(tmax, sj);
            // ---- immediate exp against current base + PV accumulate ----
            float p = ex2(sj - mi);              // masked -> ex2(-huge) = 0
            l += p;
            uint64_t p2 = pack2(p, p);
            const ulonglong2* vr = (const ulonglong2*)(Vs + j * 64);
#pragma unroll
            for (int d = 0; d < 16; ++d) {
                ulonglong2 vv = vr[d];
                fma2(o2[2 * d],     p2, vv.x);
                fma2(o2[2 * d + 1], p2, vv.y);
            }
        }

        // ---- deferred rescale: one correction per tile ----
        float corr = ex2(mi - tmax);             // tmax >= mi  ->  corr <= 1
        mi = tmax;
        l *= corr;
        uint64_t cc = pack2(corr, corr);
#pragma unroll
        for (int d = 0; d < 32; ++d) mul2(o2[d], o2[d], cc);
    }

    float inv = 1.f / l;
    float4* op = (float4*)(Og + ((size_t)(b * Sn + qg)) * En + h * Dn);
#pragma unroll
    for (int i = 0; i < 16; ++i) {
        float2 lo = unpack2(o2[2 * i]);
        float2 hi = unpack2(o2[2 * i + 1]);
        float4 v;
        v.x = lo.x * inv; v.y = lo.y * inv;
        v.z = hi.x * inv; v.w = hi.y * inv;
        op[i] = v;
    }
}

// ---------------------------------------------------------------------------
// Final head: out[m] = X[m,:] . W_out[:,0] + b_out   (warp per row)
// ---------------------------------------------------------------------------
__global__ void head_kernel(const float* __restrict__ X,
                            const float* __restrict__ Wout,
                            const float* __restrict__ bout,
                            float* __restrict__ out) {
    int gw = (blockIdx.x * blockDim.x + threadIdx.x) >> 5;
    int lane = threadIdx.x & 31;
    if (gw >= Mn) return;
    const float4* xr = (const float4*)(X + (size_t)gw * En);
    const float4* w4 = (const float4*)Wout;
    float acc = 0.f;
#pragma unroll
    for (int i = 0; i < 4; ++i) {
        float4 xv = xr[lane + i * 32];
        float4 wv = w4[lane + i * 32];
        acc += xv.x * wv.x + xv.y * wv.y + xv.z * wv.z + xv.w * wv.w;
    }
#pragma unroll
    for (int o = 16; o > 0; o >>= 1)
        acc += __shfl_xor_sync(0xffffffffu, acc, o);
    if (lane == 0) out[gw] = acc + bout[0];
}

// ---------------------------------------------------------------------------
// Launch
// ---------------------------------------------------------------------------
extern "C" void kernel_launch(void* const* d_in, const int* in_sizes, int n_in,
                              void* d_out, int out_size) {
    const int*   tok   = (const int*)d_in[0];
    const float* table = (const float*)d_in[1];
    const float* Wq    = (const float*)d_in[2];
    const float* bq    = (const float*)d_in[3];
    const float* Wk    = (const float*)d_in[4];
    const float* bk    = (const float*)d_in[5];
    const float* Wv    = (const float*)d_in[6];
    const float* bv    = (const float*)d_in[7];
    const float* Wo    = (const float*)d_in[8];
    const float* bo    = (const float*)d_in[9];
    const float* Wout  = (const float*)d_in[10];
    const float* bout  = (const float*)d_in[11];
    float* out = (float*)d_out;

    void* base = nullptr;
    cudaGetSymbolAddress(&base, g_buf);   // not a stream op: capture-safe
    float* X  = (float*)base;
    float* Qb = X + ME;
    float* Kb = X + 2 * ME;
    float* Vb = X + 3 * ME;
    float* Ab = X + 4 * ME;
    float* PE = X + 5 * ME;

    static bool attr_done = false;
    if (!attr_done) {
        cudaFuncSetAttribute(attn_kernel, cudaFuncAttributeMaxDynamicSharedMemorySize, ATT_SMEM);
        attr_done = true;
    }

    pe_kernel<<<(Sn * En + 255) / 256, 256>>>(PE);
    embed_kernel<<<(Mn * (En / 4) + 255) / 256, 256>>>(tok, table, PE, X);

    dim3 gg(En / 128, Mn / 128);   // (4, 256)
    dim3 ag(Sn / 128, Hn, Bn);     // (8, 8, 32)
    for (int l = 0; l < Ln; ++l) {
        const float* wq = Wq + (size_t)l * En * En; const float* bql = bq + l * En;
        const float* wk = Wk + (size_t)l * En * En; const float* bkl = bk + l * En;
        const float* wv = Wv + (size_t)l * En * En; const float* bvl = bv + l * En;
        const float* wo = Wo + (size_t)l * En * En; const float* bol = bo + l * En;
        gemm512<false><<<gg, 256>>>(X,  wq, bql, nullptr, Qb);
        gemm512<false><<<gg, 256>>>(X,  wk, bkl, nullptr, Kb);
        gemm512<false><<<gg, 256>>>(X,  wv, bvl, nullptr, Vb);
        attn_kernel<<<ag, 128, ATT_SMEM>>>(Qb, Kb, Vb, Ab);
        gemm512<true><<<gg, 256>>>(Ab, wo, bol, X, X);   // X = X + relu(attn@Wo+bo)
    }
    head_kernel<<<(Mn * 32 + 255) / 256, 256>>>(X, Wout, bout, out);
}